// round 7
// baseline (speedup 1.0000x reference)
#include <cuda_runtime.h>
#include <cstdint>

#define H 128
#define HEADS1 4
#define NTYPE 50
#define MZN 32
#define MAXN 64
#define BATCH 16
#define G_NUM 512            // BATCH*MZN
#define N_NODES 32768        // G_NUM*MAXN
#define E_EDGES 262144
#define TAB_ROWS 640         // 51 type rows + 512 start rows = 563, padded

// ---------------- scratch (device globals; no allocation allowed) ------------
__device__ float g_xtab[TAB_ROWS * H];
__device__ float g_tv[G_NUM * 2 * H];           // [512][256]: ve | te concat
__device__ float g_xp1[TAB_ROWS * HEADS1 * H];  // 640x512 projected table (1.3 MB)
__device__ float g_als1[TAB_ROWS * HEADS1];
__device__ float g_ald1[TAB_ROWS * HEADS1];
__device__ int   g_rowid[N_NODES];
__device__ float g_x2[N_NODES * HEADS1 * H];    // 64 MB
__device__ float g_xp2[N_NODES * H];            // 16 MB (L2-resident)
__device__ float g_als2[N_NODES];
__device__ float g_ald2[N_NODES];
__device__ float g_x3[N_NODES * H];             // 16 MB
__device__ float g_pooled[G_NUM * H];
__device__ int   g_deg[N_NODES];
__device__ int   g_off[N_NODES + 1];
__device__ int   g_cur[N_NODES];
__device__ int   g_csr[E_EDGES];
__device__ int   g_csr_rid[E_EDGES];            // rowid-translated sources (layer 1)

__device__ __forceinline__ float lrelu02(float x) { return x > 0.f ? x : 0.2f * x; }
__device__ __forceinline__ float eluf(float x)    { return x > 0.f ? x : expm1f(x); }

// ---------------- small encoder: embW rows ----------------------------------
__global__ void embw_kernel(const float* __restrict__ emb, const float* __restrict__ Wnode,
                            const float* __restrict__ bnode) {
    int r = blockIdx.x, c = threadIdx.x;
    __shared__ float er[H];
    er[c] = emb[r * H + c];
    __syncthreads();
    float s = bnode[c];
    #pragma unroll 4
    for (int k = 0; k < H; k++) s += er[k] * Wnode[k * H + c];
    g_xtab[r * H + c] = s;
}

__global__ void ln_tab_kernel(const float* __restrict__ ln_g, const float* __restrict__ ln_b) {
    int i = blockIdx.x, c = threadIdx.x;
    float h = g_xtab[i * H + c];
    __shared__ float red[H];
    red[c] = h; __syncthreads();
    for (int o = 64; o; o >>= 1) { if (c < o) red[c] += red[c + o]; __syncthreads(); }
    float mu = red[0] * (1.f / H);
    __syncthreads();
    float dh = h - mu;
    red[c] = dh * dh; __syncthreads();
    for (int o = 64; o; o >>= 1) { if (c < o) red[c] += red[c + o]; __syncthreads(); }
    float var = red[0] * (1.f / H);
    g_xtab[i * H + c] = dh * rsqrtf(var + 1e-6f) * ln_g[c] + ln_b[c];
}

// rowid + CSR counters reset, fused
__global__ void rowid_kernel(const int* __restrict__ m_idx) {
    int i = blockIdx.x * blockDim.x + threadIdx.x;
    if (i < N_NODES) {
        g_rowid[i] = ((i & 63) == 0) ? (51 + (i >> 6)) : m_idx[i];
        g_deg[i] = 0;
        g_cur[i] = 0;
    }
}

// ---------------- fp32 SGEMM, double-buffered smem pipeline ------------------
// C[M,Nc] = A[M,K] @ B[K,Nc] (+ bias[col] if non-null), C row stride = ldc.
// BM=BN=128, BK=8, 256 threads, 8x8 microtile. M%128==0, Nc%128==0, K%8==0.
// SCORES epilogue: each block column spans exactly one head's 128 output
// columns (Nc/128 heads), per-row score dots with asrc/adst for head
// blockIdx.x reduce across the 16 tx lanes by shfl (tx = lane&15; xor offsets
// 8..1 stay within each half-warp's row group). Writes als/ald[r*NHS+head].
template <bool SCORES>
__global__ __launch_bounds__(256) void sgemm128(const float* __restrict__ A,
                                                const float* __restrict__ B,
                                                float* __restrict__ C,
                                                int M, int Nc, int K, int ldc,
                                                const float* __restrict__ bias,
                                                const float* __restrict__ asrc,
                                                const float* __restrict__ adst,
                                                float* __restrict__ als,
                                                float* __restrict__ ald) {
    __shared__ float As[2][8][128];
    __shared__ float Bs[2][8][132];
    const int bx = blockIdx.x * 128, by = blockIdx.y * 128;
    const int tid = threadIdx.x;
    const int arow = tid >> 1, ak = (tid & 1) * 4;       // A: 128 rows x 8 k
    const int brow = tid >> 5, bcol = (tid & 31) * 4;    // B: 8 k x 128 cols
    const int tx = tid & 15, ty = tid >> 4;
    float acc[8][8] = {};

    const float* aptr = &A[(size_t)(by + arow) * K + ak];
    const float* bptr = &B[(size_t)brow * Nc + bx + bcol];

    float4 a4 = *reinterpret_cast<const float4*>(aptr);
    float4 b4 = *reinterpret_cast<const float4*>(bptr);
    As[0][ak + 0][arow] = a4.x; As[0][ak + 1][arow] = a4.y;
    As[0][ak + 2][arow] = a4.z; As[0][ak + 3][arow] = a4.w;
    *reinterpret_cast<float4*>(&Bs[0][brow][bcol]) = b4;
    __syncthreads();

    const int nIter = K / 8;
    for (int it = 0; it < nIter; it++) {
        int cur = it & 1, nxt = cur ^ 1;
        if (it + 1 < nIter) {
            a4 = *reinterpret_cast<const float4*>(aptr + (size_t)(it + 1) * 8);
            b4 = *reinterpret_cast<const float4*>(bptr + (size_t)(it + 1) * 8 * Nc);
        }
        #pragma unroll
        for (int k = 0; k < 8; k++) {
            float4 a0 = *reinterpret_cast<const float4*>(&As[cur][k][ty * 8]);
            float4 a1 = *reinterpret_cast<const float4*>(&As[cur][k][ty * 8 + 4]);
            float4 r0 = *reinterpret_cast<const float4*>(&Bs[cur][k][tx * 8]);
            float4 r1 = *reinterpret_cast<const float4*>(&Bs[cur][k][tx * 8 + 4]);
            float av[8] = {a0.x, a0.y, a0.z, a0.w, a1.x, a1.y, a1.z, a1.w};
            float bv[8] = {r0.x, r0.y, r0.z, r0.w, r1.x, r1.y, r1.z, r1.w};
            #pragma unroll
            for (int i = 0; i < 8; i++)
                #pragma unroll
                for (int j = 0; j < 8; j++) acc[i][j] += av[i] * bv[j];
        }
        if (it + 1 < nIter) {
            As[nxt][ak + 0][arow] = a4.x; As[nxt][ak + 1][arow] = a4.y;
            As[nxt][ak + 2][arow] = a4.z; As[nxt][ak + 3][arow] = a4.w;
            *reinterpret_cast<float4*>(&Bs[nxt][brow][bcol]) = b4;
        }
        __syncthreads();
    }

    if (bias) {
        float4 bb0 = *reinterpret_cast<const float4*>(&bias[bx + tx * 8]);
        float4 bb1 = *reinterpret_cast<const float4*>(&bias[bx + tx * 8 + 4]);
        #pragma unroll
        for (int i = 0; i < 8; i++) {
            acc[i][0] += bb0.x; acc[i][1] += bb0.y; acc[i][2] += bb0.z; acc[i][3] += bb0.w;
            acc[i][4] += bb1.x; acc[i][5] += bb1.y; acc[i][6] += bb1.z; acc[i][7] += bb1.w;
        }
    }
    #pragma unroll
    for (int i = 0; i < 8; i++) {
        float* crow = &C[(size_t)(by + ty * 8 + i) * ldc + bx + tx * 8];
        *reinterpret_cast<float4*>(crow)     = make_float4(acc[i][0], acc[i][1], acc[i][2], acc[i][3]);
        *reinterpret_cast<float4*>(crow + 4) = make_float4(acc[i][4], acc[i][5], acc[i][6], acc[i][7]);
    }
    if (SCORES) {
        const int head = blockIdx.x;          // block column == head index
        const int nhs = Nc >> 7;              // number of heads = Nc/128
        float w1[8], w2[8];
        #pragma unroll
        for (int j = 0; j < 8; j++) {
            w1[j] = asrc[head * H + tx * 8 + j];
            w2[j] = adst[head * H + tx * 8 + j];
        }
        #pragma unroll
        for (int i = 0; i < 8; i++) {
            float s1 = 0.f, s2 = 0.f;
            #pragma unroll
            for (int j = 0; j < 8; j++) { s1 += acc[i][j] * w1[j]; s2 += acc[i][j] * w2[j]; }
            #pragma unroll
            for (int o = 8; o; o >>= 1) {
                s1 += __shfl_xor_sync(0xffffffffu, s1, o);
                s2 += __shfl_xor_sync(0xffffffffu, s2, o);
            }
            if (tx == 0) {
                int r = by + ty * 8 + i;
                als[r * nhs + head] = s1;
                ald[r * nhs + head] = s2;
            }
        }
    }
}

// ---------------- CSR build (by dst) ----------------------------------------
__global__ void hist_kernel(const int* __restrict__ ei) {
    int e = blockIdx.x * blockDim.x + threadIdx.x;
    if (e < E_EDGES) atomicAdd(&g_deg[ei[E_EDGES + e]], 1);
}
__global__ void scan_kernel() {
    __shared__ int part[1024];
    int tid = threadIdx.x;
    int base = tid * 32;
    int local[32];
    int s = 0;
    #pragma unroll
    for (int i = 0; i < 32; i++) { local[i] = s; s += g_deg[base + i]; }
    part[tid] = s;
    __syncthreads();
    for (int off = 1; off < 1024; off <<= 1) {
        int v = 0;
        if (tid >= off) v = part[tid - off];
        __syncthreads();
        part[tid] += v;
        __syncthreads();
    }
    int pre = (tid == 0) ? 0 : part[tid - 1];
    #pragma unroll
    for (int i = 0; i < 32; i++) g_off[base + i] = pre + local[i];
    if (tid == 1023) g_off[N_NODES] = part[1023];
}
// scatter raw src AND rowid-translated src (for layer-1 table indirection)
__global__ void scatter_kernel(const int* __restrict__ ei) {
    int e = blockIdx.x * blockDim.x + threadIdx.x;
    if (e < E_EDGES) {
        int s = ei[e];
        int d = ei[E_EDGES + e];
        int pos = g_off[d] + atomicAdd(&g_cur[d], 1);
        g_csr[pos] = s;
        g_csr_rid[pos] = g_rowid[s];
    }
}

// ---------------- GAT aggregation: one warp per destination node -------------
// Softmax without max-shift (shift-invariant; O(1) scores, no overflow risk).
// 2-stage software pipeline: next iteration's index, score, and feature
// vectors are issued before the current exp/FMA chain.
template <int NH, bool IND>
__global__ __launch_bounds__(256) void gat_agg(const float* __restrict__ xp,
                                               const float* __restrict__ als,
                                               const float* __restrict__ ald,
                                               const float* __restrict__ bias,
                                               float* __restrict__ out,
                                               const int* __restrict__ csr_idx) {
    __shared__ float s_als[IND ? TAB_ROWS * NH : 1];
    if (IND) {
        for (int i = threadIdx.x; i < TAB_ROWS * NH; i += 256) s_als[i] = als[i];
        __syncthreads();
    }
    int d = (blockIdx.x * blockDim.x + threadIdx.x) >> 5;
    int lane = threadIdx.x & 31;
    if (d >= N_NODES) return;
    const int beg = g_off[d], end = g_off[d + 1];
    const int rd = IND ? g_rowid[d] : d;
    float aldv[NH], denom[NH];
    float4 acc[NH];
    #pragma unroll
    for (int h = 0; h < NH; h++) {
        aldv[h] = ald[rd * NH + h];
        denom[h] = 0.f;
        acc[h] = make_float4(0.f, 0.f, 0.f, 0.f);
    }
    const float4* xp4 = reinterpret_cast<const float4*>(xp);

    // pipeline stage 0: self-loop
    int rs_cur = rd;
    float sc_cur[NH];
    float4 v_cur[NH];
    #pragma unroll
    for (int h = 0; h < NH; h++) {
        sc_cur[h] = IND ? s_als[rs_cur * NH + h] : als[rs_cur * NH + h];
        v_cur[h] = xp4[(size_t)rs_cur * (NH * 32) + h * 32 + lane];
    }
    #pragma unroll 1
    for (int i = beg; i <= end; i++) {
        int rs_nxt = 0;
        float sc_nxt[NH];
        float4 v_nxt[NH];
        if (i < end) {
            rs_nxt = csr_idx[i];
            #pragma unroll
            for (int h = 0; h < NH; h++) {
                sc_nxt[h] = IND ? s_als[rs_nxt * NH + h] : als[rs_nxt * NH + h];
                v_nxt[h] = xp4[(size_t)rs_nxt * (NH * 32) + h * 32 + lane];
            }
        }
        #pragma unroll
        for (int h = 0; h < NH; h++) {
            float e = expf(lrelu02(sc_cur[h] + aldv[h]));
            denom[h] += e;
            acc[h].x += v_cur[h].x * e;
            acc[h].y += v_cur[h].y * e;
            acc[h].z += v_cur[h].z * e;
            acc[h].w += v_cur[h].w * e;
        }
        rs_cur = rs_nxt;
        #pragma unroll
        for (int h = 0; h < NH; h++) { sc_cur[h] = sc_nxt[h]; v_cur[h] = v_nxt[h]; }
    }
    #pragma unroll
    for (int h = 0; h < NH; h++) {
        int c = h * H + lane * 4;
        float inv = 1.f / denom[h];
        float4 bv = *reinterpret_cast<const float4*>(&bias[c]);
        float4 o;
        o.x = eluf(acc[h].x * inv + bv.x);
        o.y = eluf(acc[h].y * inv + bv.y);
        o.z = eluf(acc[h].z * inv + bv.z);
        o.w = eluf(acc[h].w * inv + bv.w);
        *reinterpret_cast<float4*>(&out[(size_t)d * (NH * H) + c]) = o;
    }
}

// ---------------- masked mean pool -------------------------------------------
__global__ void pool_kernel(const int* __restrict__ m_idx, const float* __restrict__ x) {
    int g = blockIdx.x, c = threadIdx.x;
    __shared__ int msk[MAXN];
    if (c < MAXN) msk[c] = (m_idx[g * MAXN + c] >= 1) ? 1 : 0;
    __syncthreads();
    float s = 0.f;
    int cnt = 0;
    #pragma unroll 4
    for (int n = 0; n < MAXN; n++) {
        if (msk[n]) { s += x[(size_t)(g * MAXN + n) * H + c]; cnt++; }
    }
    g_pooled[g * H + c] = s / (float)cnt;
}

// ---------------- output head ------------------------------------------------
__global__ void out_kernel(const float* __restrict__ Wo1, const float* __restrict__ bo1,
                           const float* __restrict__ Wo2, const float* __restrict__ bo2,
                           float* __restrict__ out) {
    int g = blockIdx.x, c = threadIdx.x; // 128 threads
    __shared__ float p[H];
    __shared__ float red[H];
    p[c] = g_pooled[g * H + c];
    __syncthreads();
    float h = bo1[c];
    #pragma unroll 4
    for (int k = 0; k < H; k++) h += p[k] * Wo1[k * H + c];
    h = h > 0.f ? h : 0.01f * h;
    red[c] = h * Wo2[c];
    __syncthreads();
    for (int o = 64; o; o >>= 1) { if (c < o) red[c] += red[c + o]; __syncthreads(); }
    if (c == 0) out[g] = red[0] + bo2[0];
}

// ---------------- launch ------------------------------------------------------
extern "C" void kernel_launch(void* const* d_in, const int* in_sizes, int n_in,
                              void* d_out, int out_size) {
    const void* p[27];
    if (n_in >= 4 && in_sizes[2] == N_NODES) {
        // setup_inputs dict order: t v m_idx edge_index Wt bt Wv bv emb Wnode
        // bnode Wstart bstart ln_g ln_b W1 a_src1 a_dst1 b1 W2 a_src2 a_dst2
        // b2 Wo1 bo1 Wo2 bo2
        static const int mp[27] = {0, 1, 4, 5, 6, 7, 8, 9, 10, 11, 12, 13, 14,
                                   15, 16, 17, 18, 19, 20, 21, 22, 23, 24, 25, 26, 2, 3};
        for (int i = 0; i < 27; i++) p[i] = d_in[mp[i]];
    } else {
        for (int i = 0; i < 27; i++) p[i] = d_in[i];
    }
    const float* t       = (const float*)p[0];
    const float* v       = (const float*)p[1];
    const float* Wt      = (const float*)p[2];
    const float* bt      = (const float*)p[3];
    const float* Wv      = (const float*)p[4];
    const float* bv      = (const float*)p[5];
    const float* emb     = (const float*)p[6];
    const float* Wnode   = (const float*)p[7];
    const float* bnode   = (const float*)p[8];
    const float* Wstart  = (const float*)p[9];
    const float* bstart  = (const float*)p[10];
    const float* ln_g    = (const float*)p[11];
    const float* ln_b    = (const float*)p[12];
    const float* W1      = (const float*)p[13];
    const float* a_src1  = (const float*)p[14];
    const float* a_dst1  = (const float*)p[15];
    const float* b1      = (const float*)p[16];
    const float* W2      = (const float*)p[17];
    const float* a_src2  = (const float*)p[18];
    const float* a_dst2  = (const float*)p[19];
    const float* b2      = (const float*)p[20];
    const float* Wo1     = (const float*)p[21];
    const float* bo1     = (const float*)p[22];
    const float* Wo2     = (const float*)p[23];
    const float* bo2     = (const float*)p[24];
    const int*   m_idx   = (const int*)p[25];
    const int*   ei      = (const int*)p[26];

    float* xtab;   cudaGetSymbolAddress((void**)&xtab,   g_xtab);
    float* tv;     cudaGetSymbolAddress((void**)&tv,     g_tv);
    float* xp1;    cudaGetSymbolAddress((void**)&xp1,    g_xp1);
    float* als1;   cudaGetSymbolAddress((void**)&als1,   g_als1);
    float* ald1;   cudaGetSymbolAddress((void**)&ald1,   g_ald1);
    float* x2buf;  cudaGetSymbolAddress((void**)&x2buf,  g_x2);
    float* xp2;    cudaGetSymbolAddress((void**)&xp2,    g_xp2);
    float* als2;   cudaGetSymbolAddress((void**)&als2,   g_als2);
    float* ald2;   cudaGetSymbolAddress((void**)&ald2,   g_ald2);
    float* x3buf;  cudaGetSymbolAddress((void**)&x3buf,  g_x3);
    int*   csr;    cudaGetSymbolAddress((void**)&csr,    g_csr);
    int*   csrrid; cudaGetSymbolAddress((void**)&csrrid, g_csr_rid);

    // encoders as tiled GEMMs (weight tiles L2-reused, not re-streamed/block):
    // g_tv[:, 0:128] = v@Wv + bv ; g_tv[:, 128:256] = t@Wt + bt
    sgemm128<false><<<dim3(1, G_NUM / 128), 256>>>(
        v, Wv, tv, G_NUM, H, 768, 2 * H, bv, nullptr, nullptr, nullptr, nullptr);
    sgemm128<false><<<dim3(1, G_NUM / 128), 256>>>(
        t, Wt, tv + H, G_NUM, H, 768, 2 * H, bt, nullptr, nullptr, nullptr, nullptr);
    // start rows: xtab[51+g] = concat(ve, te) @ Wstart + bstart
    sgemm128<false><<<dim3(1, G_NUM / 128), 256>>>(
        tv, Wstart, xtab + 51 * H, G_NUM, H, 2 * H, H, bstart,
        nullptr, nullptr, nullptr, nullptr);
    // type rows + LN + per-node rowid (+ counter reset)
    embw_kernel<<<NTYPE + 1, H>>>(emb, Wnode, bnode);
    ln_tab_kernel<<<576, H>>>(ln_g, ln_b);
    rowid_kernel<<<(N_NODES + 255) / 256, 256>>>(m_idx);

    // CSR build (by dst), with rowid-translated twin
    hist_kernel<<<E_EDGES / 256, 256>>>(ei);
    scan_kernel<<<1, 1024>>>();
    scatter_kernel<<<E_EDGES / 256, 256>>>(ei);

    // GAT layer 1 — projection over the 640-row table, scores fused per-head
    sgemm128<true><<<dim3(HEADS1 * H / 128, TAB_ROWS / 128), 256>>>(
        xtab, W1, xp1, TAB_ROWS, HEADS1 * H, H, HEADS1 * H, nullptr,
        a_src1, a_dst1, als1, ald1);
    gat_agg<HEADS1, true><<<(N_NODES * 32) / 256, 256>>>(xp1, als1, ald1, b1, x2buf, csrrid);

    // GAT layer 2 — full GEMM with fused score epilogue (Nc==128, one head)
    sgemm128<true><<<dim3(1, N_NODES / 128), 256>>>(
        x2buf, W2, xp2, N_NODES, H, HEADS1 * H, H, nullptr,
        a_src2, a_dst2, als2, ald2);
    gat_agg<1, false><<<(N_NODES * 32) / 256, 256>>>(xp2, als2, ald2, b2, x3buf, csr);

    // pool + head
    pool_kernel<<<G_NUM, H>>>(m_idx, x3buf);
    out_kernel<<<G_NUM, H>>>(Wo1, bo1, Wo2, bo2, (float*)d_out);
}

// round 12
// speedup vs baseline: 1.3685x; 1.3685x over previous
#include <cuda_runtime.h>
#include <cstdint>

#define H 128
#define HEADS1 4
#define NTYPE 50
#define MZN 32
#define MAXN 64
#define BATCH 16
#define G_NUM 512            // BATCH*MZN
#define N_NODES 32768        // G_NUM*MAXN
#define E_EDGES 262144
#define TAB_ROWS 640         // 51 type rows + 512 start rows = 563, padded
#define GPB 4                // graphs per encoder block

// ---------------- scratch (device globals; no allocation allowed) ------------
__device__ float g_xtab[TAB_ROWS * H];          // LN'd distinct rows (pad rows stay 0)
__device__ float g_xp1[TAB_ROWS * HEADS1 * H];  // 640x512 projected table (1.3 MB)
__device__ float g_als1[TAB_ROWS * HEADS1];
__device__ float g_ald1[TAB_ROWS * HEADS1];
__device__ int   g_rowid[N_NODES];
__device__ float g_x2[N_NODES * HEADS1 * H];    // 64 MB
__device__ float g_xp2[N_NODES * H];            // 16 MB (L2-resident)
__device__ float g_als2[N_NODES];
__device__ float g_ald2[N_NODES];
__device__ float g_x3[N_NODES * H];             // 16 MB
__device__ int   g_deg[N_NODES];
__device__ int   g_off[N_NODES + 1];
__device__ int   g_cur[N_NODES];
__device__ int   g_csr[E_EDGES];
__device__ int   g_csr_rid[E_EDGES];            // rowid-translated sources (layer 1)

__device__ __forceinline__ float lrelu02(float x) { return x > 0.f ? x : 0.2f * x; }
__device__ __forceinline__ float eluf(float x)    { return x > 0.f ? x : expm1f(x); }

// ---------------- fused encoder: start rows (4 graphs/block) + embW rows -----
// blocks [0,128): graphs 4*b..4*b+3 -> te/ve -> start -> LN -> xtab[51+g]
// blocks [128,179): emb row r=b-128 -> @Wnode -> LN -> xtab[r]
__global__ __launch_bounds__(128) void encoder_kernel(
    const float* __restrict__ t, const float* __restrict__ v,
    const float* __restrict__ Wt, const float* __restrict__ bt,
    const float* __restrict__ Wv, const float* __restrict__ bv,
    const float* __restrict__ Wstart, const float* __restrict__ bstart,
    const float* __restrict__ emb, const float* __restrict__ Wnode,
    const float* __restrict__ bnode,
    const float* __restrict__ ln_g, const float* __restrict__ ln_b) {
    const int c = threadIdx.x;          // 128 threads = one column each
    __shared__ float red[GPB][H];

    if (blockIdx.x >= 128) {
        // ---- embW row + LN ----
        int r = blockIdx.x - 128;
        __shared__ float er[H];
        er[c] = emb[r * H + c];
        __syncthreads();
        float s = bnode[c];
        #pragma unroll 16
        for (int k = 0; k < H; k++) s += er[k] * Wnode[k * H + c];
        red[0][c] = s; __syncthreads();
        for (int o = 64; o; o >>= 1) { if (c < o) red[0][c] += red[0][c + o]; __syncthreads(); }
        float mu = red[0][0] * (1.f / H);
        __syncthreads();
        float dh = s - mu;
        red[0][c] = dh * dh; __syncthreads();
        for (int o = 64; o; o >>= 1) { if (c < o) red[0][c] += red[0][c + o]; __syncthreads(); }
        float var = red[0][0] * (1.f / H);
        g_xtab[r * H + c] = dh * rsqrtf(var + 1e-6f) * ln_g[c] + ln_b[c];
        return;
    }

    // ---- start rows: 4 graphs per block ----
    const int g0 = blockIdx.x * GPB;
    __shared__ float ts[GPB][768], vs[GPB][768];
    #pragma unroll
    for (int j = 0; j < GPB; j++)
        for (int k = c; k < 768; k += H) {
            ts[j][k] = t[(size_t)(g0 + j) * 768 + k];
            vs[j][k] = v[(size_t)(g0 + j) * 768 + k];
        }
    __syncthreads();

    float te[GPB], ve[GPB];
    #pragma unroll
    for (int j = 0; j < GPB; j++) { te[j] = bt[c]; ve[j] = bv[c]; }
    #pragma unroll 4
    for (int k = 0; k < 768; k++) {
        float wt = Wt[k * H + c], wv = Wv[k * H + c];   // loaded once, reused 4x
        #pragma unroll
        for (int j = 0; j < GPB; j++) {
            te[j] += ts[j][k] * wt;
            ve[j] += vs[j][k] * wv;
        }
    }
    __shared__ float tes[GPB][H], ves[GPB][H];
    #pragma unroll
    for (int j = 0; j < GPB; j++) { tes[j][c] = te[j]; ves[j][c] = ve[j]; }
    __syncthreads();

    float st[GPB];
    #pragma unroll
    for (int j = 0; j < GPB; j++) st[j] = bstart[c];
    #pragma unroll 4
    for (int k = 0; k < H; k++) {
        float w1 = Wstart[k * H + c], w2 = Wstart[(H + k) * H + c];
        #pragma unroll
        for (int j = 0; j < GPB; j++) st[j] += ves[j][k] * w1 + tes[j][k] * w2;
    }

    // LN all 4 rows (reductions done in parallel across j)
    #pragma unroll
    for (int j = 0; j < GPB; j++) red[j][c] = st[j];
    __syncthreads();
    for (int o = 64; o; o >>= 1) {
        if (c < o) {
            #pragma unroll
            for (int j = 0; j < GPB; j++) red[j][c] += red[j][c + o];
        }
        __syncthreads();
    }
    float mu[GPB];
    #pragma unroll
    for (int j = 0; j < GPB; j++) mu[j] = red[j][0] * (1.f / H);
    __syncthreads();
    float dh[GPB];
    #pragma unroll
    for (int j = 0; j < GPB; j++) { dh[j] = st[j] - mu[j]; red[j][c] = dh[j] * dh[j]; }
    __syncthreads();
    for (int o = 64; o; o >>= 1) {
        if (c < o) {
            #pragma unroll
            for (int j = 0; j < GPB; j++) red[j][c] += red[j][c + o];
        }
        __syncthreads();
    }
    float lg = ln_g[c], lb = ln_b[c];
    #pragma unroll
    for (int j = 0; j < GPB; j++) {
        float var = red[j][0] * (1.f / H);
        g_xtab[(51 + g0 + j) * H + c] = dh[j] * rsqrtf(var + 1e-6f) * lg + lb;
    }
}

// rowid + CSR counters reset, fused
__global__ void rowid_kernel(const int* __restrict__ m_idx) {
    int i = blockIdx.x * blockDim.x + threadIdx.x;
    if (i < N_NODES) {
        g_rowid[i] = ((i & 63) == 0) ? (51 + (i >> 6)) : m_idx[i];
        g_deg[i] = 0;
        g_cur[i] = 0;
    }
}

// ---------------- fp32 SGEMM, double-buffered smem pipeline ------------------
// C[M,Nc] = A[M,K] @ B[K,Nc] (+ bias[col] if non-null), C row stride = ldc.
// BM=BN=128, BK=8, 256 threads, 8x8 microtile. M%128==0, Nc%128==0, K%8==0.
// SCORES epilogue: each block column spans exactly one head's 128 output
// columns (Nc/128 heads), per-row score dots with asrc/adst for head
// blockIdx.x reduce across the 16 tx lanes by shfl (tx = lane&15; xor offsets
// 8..1 stay within each half-warp's row group). Writes als/ald[r*NHS+head].
template <bool SCORES>
__global__ __launch_bounds__(256) void sgemm128(const float* __restrict__ A,
                                                const float* __restrict__ B,
                                                float* __restrict__ C,
                                                int M, int Nc, int K, int ldc,
                                                const float* __restrict__ bias,
                                                const float* __restrict__ asrc,
                                                const float* __restrict__ adst,
                                                float* __restrict__ als,
                                                float* __restrict__ ald) {
    __shared__ float As[2][8][128];
    __shared__ float Bs[2][8][132];
    const int bx = blockIdx.x * 128, by = blockIdx.y * 128;
    const int tid = threadIdx.x;
    const int arow = tid >> 1, ak = (tid & 1) * 4;       // A: 128 rows x 8 k
    const int brow = tid >> 5, bcol = (tid & 31) * 4;    // B: 8 k x 128 cols
    const int tx = tid & 15, ty = tid >> 4;
    float acc[8][8] = {};

    const float* aptr = &A[(size_t)(by + arow) * K + ak];
    const float* bptr = &B[(size_t)brow * Nc + bx + bcol];

    float4 a4 = *reinterpret_cast<const float4*>(aptr);
    float4 b4 = *reinterpret_cast<const float4*>(bptr);
    As[0][ak + 0][arow] = a4.x; As[0][ak + 1][arow] = a4.y;
    As[0][ak + 2][arow] = a4.z; As[0][ak + 3][arow] = a4.w;
    *reinterpret_cast<float4*>(&Bs[0][brow][bcol]) = b4;
    __syncthreads();

    const int nIter = K / 8;
    for (int it = 0; it < nIter; it++) {
        int cur = it & 1, nxt = cur ^ 1;
        if (it + 1 < nIter) {
            a4 = *reinterpret_cast<const float4*>(aptr + (size_t)(it + 1) * 8);
            b4 = *reinterpret_cast<const float4*>(bptr + (size_t)(it + 1) * 8 * Nc);
        }
        #pragma unroll
        for (int k = 0; k < 8; k++) {
            float4 a0 = *reinterpret_cast<const float4*>(&As[cur][k][ty * 8]);
            float4 a1 = *reinterpret_cast<const float4*>(&As[cur][k][ty * 8 + 4]);
            float4 r0 = *reinterpret_cast<const float4*>(&Bs[cur][k][tx * 8]);
            float4 r1 = *reinterpret_cast<const float4*>(&Bs[cur][k][tx * 8 + 4]);
            float av[8] = {a0.x, a0.y, a0.z, a0.w, a1.x, a1.y, a1.z, a1.w};
            float bv[8] = {r0.x, r0.y, r0.z, r0.w, r1.x, r1.y, r1.z, r1.w};
            #pragma unroll
            for (int i = 0; i < 8; i++)
                #pragma unroll
                for (int j = 0; j < 8; j++) acc[i][j] += av[i] * bv[j];
        }
        if (it + 1 < nIter) {
            As[nxt][ak + 0][arow] = a4.x; As[nxt][ak + 1][arow] = a4.y;
            As[nxt][ak + 2][arow] = a4.z; As[nxt][ak + 3][arow] = a4.w;
            *reinterpret_cast<float4*>(&Bs[nxt][brow][bcol]) = b4;
        }
        __syncthreads();
    }

    if (bias) {
        float4 bb0 = *reinterpret_cast<const float4*>(&bias[bx + tx * 8]);
        float4 bb1 = *reinterpret_cast<const float4*>(&bias[bx + tx * 8 + 4]);
        #pragma unroll
        for (int i = 0; i < 8; i++) {
            acc[i][0] += bb0.x; acc[i][1] += bb0.y; acc[i][2] += bb0.z; acc[i][3] += bb0.w;
            acc[i][4] += bb1.x; acc[i][5] += bb1.y; acc[i][6] += bb1.z; acc[i][7] += bb1.w;
        }
    }
    #pragma unroll
    for (int i = 0; i < 8; i++) {
        float* crow = &C[(size_t)(by + ty * 8 + i) * ldc + bx + tx * 8];
        *reinterpret_cast<float4*>(crow)     = make_float4(acc[i][0], acc[i][1], acc[i][2], acc[i][3]);
        *reinterpret_cast<float4*>(crow + 4) = make_float4(acc[i][4], acc[i][5], acc[i][6], acc[i][7]);
    }
    if (SCORES) {
        const int head = blockIdx.x;          // block column == head index
        const int nhs = Nc >> 7;              // number of heads = Nc/128
        float w1[8], w2[8];
        #pragma unroll
        for (int j = 0; j < 8; j++) {
            w1[j] = asrc[head * H + tx * 8 + j];
            w2[j] = adst[head * H + tx * 8 + j];
        }
        #pragma unroll
        for (int i = 0; i < 8; i++) {
            float s1 = 0.f, s2 = 0.f;
            #pragma unroll
            for (int j = 0; j < 8; j++) { s1 += acc[i][j] * w1[j]; s2 += acc[i][j] * w2[j]; }
            #pragma unroll
            for (int o = 8; o; o >>= 1) {
                s1 += __shfl_xor_sync(0xffffffffu, s1, o);
                s2 += __shfl_xor_sync(0xffffffffu, s2, o);
            }
            if (tx == 0) {
                int r = by + ty * 8 + i;
                als[r * nhs + head] = s1;
                ald[r * nhs + head] = s2;
            }
        }
    }
}

// ---------------- CSR build (by dst) ----------------------------------------
__global__ void hist_kernel(const int* __restrict__ ei) {
    int e = blockIdx.x * blockDim.x + threadIdx.x;
    if (e < E_EDGES) atomicAdd(&g_deg[ei[E_EDGES + e]], 1);
}
__global__ void scan_kernel() {
    __shared__ int part[1024];
    int tid = threadIdx.x;
    int base = tid * 32;
    int local[32];
    int s = 0;
    #pragma unroll
    for (int i = 0; i < 32; i++) { local[i] = s; s += g_deg[base + i]; }
    part[tid] = s;
    __syncthreads();
    for (int off = 1; off < 1024; off <<= 1) {
        int v = 0;
        if (tid >= off) v = part[tid - off];
        __syncthreads();
        part[tid] += v;
        __syncthreads();
    }
    int pre = (tid == 0) ? 0 : part[tid - 1];
    #pragma unroll
    for (int i = 0; i < 32; i++) g_off[base + i] = pre + local[i];
    if (tid == 1023) g_off[N_NODES] = part[1023];
}
// scatter raw src AND rowid-translated src (for layer-1 table indirection)
__global__ void scatter_kernel(const int* __restrict__ ei) {
    int e = blockIdx.x * blockDim.x + threadIdx.x;
    if (e < E_EDGES) {
        int s = ei[e];
        int d = ei[E_EDGES + e];
        int pos = g_off[d] + atomicAdd(&g_cur[d], 1);
        g_csr[pos] = s;
        g_csr_rid[pos] = g_rowid[s];
    }
}

// ---------------- GAT aggregation: one warp per destination node -------------
// Softmax without max-shift (shift-invariant; O(1) scores, no overflow risk).
// __expf (MUFU.EX2 fast path) for the hot-loop softmax weights: rel err
// ~2^-21, cancels further in the num/denom ratio; ~20 inst saved per call.
// 2-stage software pipeline: next iteration's index, score, and feature
// vectors are issued before the current exp/FMA chain.
template <int NH, bool IND>
__global__ __launch_bounds__(256) void gat_agg(const float* __restrict__ xp,
                                               const float* __restrict__ als,
                                               const float* __restrict__ ald,
                                               const float* __restrict__ bias,
                                               float* __restrict__ out,
                                               const int* __restrict__ csr_idx) {
    __shared__ float s_als[IND ? TAB_ROWS * NH : 1];
    if (IND) {
        for (int i = threadIdx.x; i < TAB_ROWS * NH; i += 256) s_als[i] = als[i];
        __syncthreads();
    }
    int d = (blockIdx.x * blockDim.x + threadIdx.x) >> 5;
    int lane = threadIdx.x & 31;
    if (d >= N_NODES) return;
    const int beg = g_off[d], end = g_off[d + 1];
    const int rd = IND ? g_rowid[d] : d;
    float aldv[NH], denom[NH];
    float4 acc[NH];
    #pragma unroll
    for (int h = 0; h < NH; h++) {
        aldv[h] = ald[rd * NH + h];
        denom[h] = 0.f;
        acc[h] = make_float4(0.f, 0.f, 0.f, 0.f);
    }
    const float4* xp4 = reinterpret_cast<const float4*>(xp);

    // pipeline stage 0: self-loop
    int rs_cur = rd;
    float sc_cur[NH];
    float4 v_cur[NH];
    #pragma unroll
    for (int h = 0; h < NH; h++) {
        sc_cur[h] = IND ? s_als[rs_cur * NH + h] : als[rs_cur * NH + h];
        v_cur[h] = xp4[(size_t)rs_cur * (NH * 32) + h * 32 + lane];
    }
    #pragma unroll 1
    for (int i = beg; i <= end; i++) {
        int rs_nxt = 0;
        float sc_nxt[NH];
        float4 v_nxt[NH];
        if (i < end) {
            rs_nxt = csr_idx[i];
            #pragma unroll
            for (int h = 0; h < NH; h++) {
                sc_nxt[h] = IND ? s_als[rs_nxt * NH + h] : als[rs_nxt * NH + h];
                v_nxt[h] = xp4[(size_t)rs_nxt * (NH * 32) + h * 32 + lane];
            }
        }
        #pragma unroll
        for (int h = 0; h < NH; h++) {
            float e = __expf(lrelu02(sc_cur[h] + aldv[h]));
            denom[h] += e;
            acc[h].x += v_cur[h].x * e;
            acc[h].y += v_cur[h].y * e;
            acc[h].z += v_cur[h].z * e;
            acc[h].w += v_cur[h].w * e;
        }
        rs_cur = rs_nxt;
        #pragma unroll
        for (int h = 0; h < NH; h++) { sc_cur[h] = sc_nxt[h]; v_cur[h] = v_nxt[h]; }
    }
    #pragma unroll
    for (int h = 0; h < NH; h++) {
        int c = h * H + lane * 4;
        float inv = 1.f / denom[h];
        float4 bv = *reinterpret_cast<const float4*>(&bias[c]);
        float4 o;
        o.x = eluf(acc[h].x * inv + bv.x);
        o.y = eluf(acc[h].y * inv + bv.y);
        o.z = eluf(acc[h].z * inv + bv.z);
        o.w = eluf(acc[h].w * inv + bv.w);
        *reinterpret_cast<float4*>(&out[(size_t)d * (NH * H) + c]) = o;
    }
}

// ---------------- fused masked mean pool + output head -----------------------
// block g: pooled[c] = mean over masked nodes of x[g*64+n][c]; then
// h = lrelu(pooled @ Wo1 + bo1); out[g] = h @ Wo2 + bo2.
__global__ __launch_bounds__(128) void pool_head_kernel(
    const int* __restrict__ m_idx, const float* __restrict__ x,
    const float* __restrict__ Wo1, const float* __restrict__ bo1,
    const float* __restrict__ Wo2, const float* __restrict__ bo2,
    float* __restrict__ out) {
    int g = blockIdx.x, c = threadIdx.x; // 128 threads
    __shared__ int msk[MAXN];
    __shared__ float p[H];
    __shared__ float red[H];
    if (c < MAXN) msk[c] = (m_idx[g * MAXN + c] >= 1) ? 1 : 0;
    __syncthreads();
    float s = 0.f;
    int cnt = 0;
    #pragma unroll 4
    for (int n = 0; n < MAXN; n++) {
        if (msk[n]) { s += x[(size_t)(g * MAXN + n) * H + c]; cnt++; }
    }
    p[c] = s / (float)cnt;
    __syncthreads();
    float h = bo1[c];
    #pragma unroll 4
    for (int k = 0; k < H; k++) h += p[k] * Wo1[k * H + c];
    h = h > 0.f ? h : 0.01f * h;
    red[c] = h * Wo2[c];
    __syncthreads();
    for (int o = 64; o; o >>= 1) { if (c < o) red[c] += red[c + o]; __syncthreads(); }
    if (c == 0) out[g] = red[0] + bo2[0];
}

// ---------------- launch ------------------------------------------------------
extern "C" void kernel_launch(void* const* d_in, const int* in_sizes, int n_in,
                              void* d_out, int out_size) {
    const void* p[27];
    if (n_in >= 4 && in_sizes[2] == N_NODES) {
        // setup_inputs dict order: t v m_idx edge_index Wt bt Wv bv emb Wnode
        // bnode Wstart bstart ln_g ln_b W1 a_src1 a_dst1 b1 W2 a_src2 a_dst2
        // b2 Wo1 bo1 Wo2 bo2
        static const int mp[27] = {0, 1, 4, 5, 6, 7, 8, 9, 10, 11, 12, 13, 14,
                                   15, 16, 17, 18, 19, 20, 21, 22, 23, 24, 25, 26, 2, 3};
        for (int i = 0; i < 27; i++) p[i] = d_in[mp[i]];
    } else {
        for (int i = 0; i < 27; i++) p[i] = d_in[i];
    }
    const float* t       = (const float*)p[0];
    const float* v       = (const float*)p[1];
    const float* Wt      = (const float*)p[2];
    const float* bt      = (const float*)p[3];
    const float* Wv      = (const float*)p[4];
    const float* bv      = (const float*)p[5];
    const float* emb     = (const float*)p[6];
    const float* Wnode   = (const float*)p[7];
    const float* bnode   = (const float*)p[8];
    const float* Wstart  = (const float*)p[9];
    const float* bstart  = (const float*)p[10];
    const float* ln_g    = (const float*)p[11];
    const float* ln_b    = (const float*)p[12];
    const float* W1      = (const float*)p[13];
    const float* a_src1  = (const float*)p[14];
    const float* a_dst1  = (const float*)p[15];
    const float* b1      = (const float*)p[16];
    const float* W2      = (const float*)p[17];
    const float* a_src2  = (const float*)p[18];
    const float* a_dst2  = (const float*)p[19];
    const float* b2      = (const float*)p[20];
    const float* Wo1     = (const float*)p[21];
    const float* bo1     = (const float*)p[22];
    const float* Wo2     = (const float*)p[23];
    const float* bo2     = (const float*)p[24];
    const int*   m_idx   = (const int*)p[25];
    const int*   ei      = (const int*)p[26];

    float* xtab;   cudaGetSymbolAddress((void**)&xtab,   g_xtab);
    float* xp1;    cudaGetSymbolAddress((void**)&xp1,    g_xp1);
    float* als1;   cudaGetSymbolAddress((void**)&als1,   g_als1);
    float* ald1;   cudaGetSymbolAddress((void**)&ald1,   g_ald1);
    float* x2buf;  cudaGetSymbolAddress((void**)&x2buf,  g_x2);
    float* xp2;    cudaGetSymbolAddress((void**)&xp2,    g_xp2);
    float* als2;   cudaGetSymbolAddress((void**)&als2,   g_als2);
    float* ald2;   cudaGetSymbolAddress((void**)&ald2,   g_ald2);
    float* x3buf;  cudaGetSymbolAddress((void**)&x3buf,  g_x3);
    int*   csr;    cudaGetSymbolAddress((void**)&csr,    g_csr);
    int*   csrrid; cudaGetSymbolAddress((void**)&csrrid, g_csr_rid);

    // 0-3: rowid (+deg/cur reset) then CSR build
    rowid_kernel<<<(N_NODES + 255) / 256, 256>>>(m_idx);
    hist_kernel<<<E_EDGES / 256, 256>>>(ei);
    scan_kernel<<<1, 1024>>>();
    scatter_kernel<<<E_EDGES / 256, 256>>>(ei);

    // 4: fused encoder (start rows x4/block + embW rows), LN in-block
    encoder_kernel<<<128 + NTYPE + 1, 128>>>(t, v, Wt, bt, Wv, bv, Wstart, bstart,
                                             emb, Wnode, bnode, ln_g, ln_b);

    // 5: GAT layer 1 projection over the 640-row table, scores fused per-head
    //    (ncu -s 5 -c 1 captures this launch: the sgemm128 template)
    sgemm128<true><<<dim3(HEADS1 * H / 128, TAB_ROWS / 128), 256>>>(
        xtab, W1, xp1, TAB_ROWS, HEADS1 * H, H, HEADS1 * H, nullptr,
        a_src1, a_dst1, als1, ald1);
    // 6: layer-1 aggregation
    gat_agg<HEADS1, true><<<(N_NODES * 32) / 256, 256>>>(xp1, als1, ald1, b1, x2buf, csrrid);

    // 7: GAT layer 2 — full GEMM with fused score epilogue (Nc==128, one head)
    sgemm128<true><<<dim3(1, N_NODES / 128), 256>>>(
        x2buf, W2, xp2, N_NODES, H, HEADS1 * H, H, nullptr,
        a_src2, a_dst2, als2, ald2);
    // 8: layer-2 aggregation
    gat_agg<1, false><<<(N_NODES * 32) / 256, 256>>>(xp2, als2, ald2, b2, x3buf, csr);

    // 9: fused pool + head
    pool_head_kernel<<<G_NUM, H>>>(m_idx, x3buf, Wo1, bo1, Wo2, bo2, (float*)d_out);
}

// round 13
// speedup vs baseline: 1.4586x; 1.0658x over previous
#include <cuda_runtime.h>
#include <cuda_bf16.h>
#include <cstdint>

#define H 128
#define HEADS1 4
#define NTYPE 50
#define MZN 32
#define MAXN 64
#define BATCH 16
#define G_NUM 512            // BATCH*MZN
#define N_NODES 32768        // G_NUM*MAXN
#define E_EDGES 262144
#define TAB_ROWS 640         // 51 type rows + 512 start rows = 563, padded
#define GPB 4                // graphs per encoder block

// ---------------- scratch (device globals; no allocation allowed) ------------
__device__ float g_xtab[TAB_ROWS * H];          // LN'd distinct rows (pad rows stay 0)
__device__ float g_xp1[TAB_ROWS * HEADS1 * H];  // 640x512 projected table (1.3 MB)
__device__ float g_als1[TAB_ROWS * HEADS1];
__device__ float g_ald1[TAB_ROWS * HEADS1];
__device__ int   g_rowid[N_NODES];
__device__ float g_x2[N_NODES * HEADS1 * H];    // 64 MB
__device__ float g_xp2[N_NODES * H];            // 16 MB (L2-resident)
__device__ float g_als2[N_NODES];
__device__ float g_ald2[N_NODES];
__device__ float g_x3[N_NODES * H];             // 16 MB
__device__ int   g_deg[N_NODES];
__device__ int   g_off[N_NODES + 1];
__device__ int   g_cur[N_NODES];
__device__ int   g_csr[E_EDGES];
__device__ int   g_csr_rid[E_EDGES];            // rowid-translated sources (layer 1)

__device__ __forceinline__ float lrelu02(float x) { return x > 0.f ? x : 0.2f * x; }
__device__ __forceinline__ float eluf(float x)    { return x > 0.f ? x : expm1f(x); }

// ---------------- fused encoder: start rows (4 graphs/block) + embW rows -----
__global__ __launch_bounds__(128) void encoder_kernel(
    const float* __restrict__ t, const float* __restrict__ v,
    const float* __restrict__ Wt, const float* __restrict__ bt,
    const float* __restrict__ Wv, const float* __restrict__ bv,
    const float* __restrict__ Wstart, const float* __restrict__ bstart,
    const float* __restrict__ emb, const float* __restrict__ Wnode,
    const float* __restrict__ bnode,
    const float* __restrict__ ln_g, const float* __restrict__ ln_b) {
    const int c = threadIdx.x;          // 128 threads = one column each
    __shared__ float red[GPB][H];

    if (blockIdx.x >= 128) {
        // ---- embW row + LN ----
        int r = blockIdx.x - 128;
        __shared__ float er[H];
        er[c] = emb[r * H + c];
        __syncthreads();
        float s = bnode[c];
        #pragma unroll 16
        for (int k = 0; k < H; k++) s += er[k] * Wnode[k * H + c];
        red[0][c] = s; __syncthreads();
        for (int o = 64; o; o >>= 1) { if (c < o) red[0][c] += red[0][c + o]; __syncthreads(); }
        float mu = red[0][0] * (1.f / H);
        __syncthreads();
        float dh = s - mu;
        red[0][c] = dh * dh; __syncthreads();
        for (int o = 64; o; o >>= 1) { if (c < o) red[0][c] += red[0][c + o]; __syncthreads(); }
        float var = red[0][0] * (1.f / H);
        g_xtab[r * H + c] = dh * rsqrtf(var + 1e-6f) * ln_g[c] + ln_b[c];
        return;
    }

    // ---- start rows: 4 graphs per block ----
    const int g0 = blockIdx.x * GPB;
    __shared__ float ts[GPB][768], vs[GPB][768];
    #pragma unroll
    for (int j = 0; j < GPB; j++)
        for (int k = c; k < 768; k += H) {
            ts[j][k] = t[(size_t)(g0 + j) * 768 + k];
            vs[j][k] = v[(size_t)(g0 + j) * 768 + k];
        }
    __syncthreads();

    float te[GPB], ve[GPB];
    #pragma unroll
    for (int j = 0; j < GPB; j++) { te[j] = bt[c]; ve[j] = bv[c]; }
    #pragma unroll 4
    for (int k = 0; k < 768; k++) {
        float wt = Wt[k * H + c], wv = Wv[k * H + c];   // loaded once, reused 4x
        #pragma unroll
        for (int j = 0; j < GPB; j++) {
            te[j] += ts[j][k] * wt;
            ve[j] += vs[j][k] * wv;
        }
    }
    __shared__ float tes[GPB][H], ves[GPB][H];
    #pragma unroll
    for (int j = 0; j < GPB; j++) { tes[j][c] = te[j]; ves[j][c] = ve[j]; }
    __syncthreads();

    float st[GPB];
    #pragma unroll
    for (int j = 0; j < GPB; j++) st[j] = bstart[c];
    #pragma unroll 4
    for (int k = 0; k < H; k++) {
        float w1 = Wstart[k * H + c], w2 = Wstart[(H + k) * H + c];
        #pragma unroll
        for (int j = 0; j < GPB; j++) st[j] += ves[j][k] * w1 + tes[j][k] * w2;
    }

    #pragma unroll
    for (int j = 0; j < GPB; j++) red[j][c] = st[j];
    __syncthreads();
    for (int o = 64; o; o >>= 1) {
        if (c < o) {
            #pragma unroll
            for (int j = 0; j < GPB; j++) red[j][c] += red[j][c + o];
        }
        __syncthreads();
    }
    float mu[GPB];
    #pragma unroll
    for (int j = 0; j < GPB; j++) mu[j] = red[j][0] * (1.f / H);
    __syncthreads();
    float dh[GPB];
    #pragma unroll
    for (int j = 0; j < GPB; j++) { dh[j] = st[j] - mu[j]; red[j][c] = dh[j] * dh[j]; }
    __syncthreads();
    for (int o = 64; o; o >>= 1) {
        if (c < o) {
            #pragma unroll
            for (int j = 0; j < GPB; j++) red[j][c] += red[j][c + o];
        }
        __syncthreads();
    }
    float lg = ln_g[c], lb = ln_b[c];
    #pragma unroll
    for (int j = 0; j < GPB; j++) {
        float var = red[j][0] * (1.f / H);
        g_xtab[(51 + g0 + j) * H + c] = dh[j] * rsqrtf(var + 1e-6f) * lg + lb;
    }
}

// rowid + CSR counters reset, fused
__global__ void rowid_kernel(const int* __restrict__ m_idx) {
    int i = blockIdx.x * blockDim.x + threadIdx.x;
    if (i < N_NODES) {
        g_rowid[i] = ((i & 63) == 0) ? (51 + (i >> 6)) : m_idx[i];
        g_deg[i] = 0;
        g_cur[i] = 0;
    }
}

// ---------------- fp32 SGEMM (layer-1: 640-row table) ------------------------
template <bool SCORES>
__global__ __launch_bounds__(256) void sgemm128(const float* __restrict__ A,
                                                const float* __restrict__ B,
                                                float* __restrict__ C,
                                                int M, int Nc, int K, int ldc,
                                                const float* __restrict__ bias,
                                                const float* __restrict__ asrc,
                                                const float* __restrict__ adst,
                                                float* __restrict__ als,
                                                float* __restrict__ ald) {
    __shared__ float As[2][8][128];
    __shared__ float Bs[2][8][132];
    const int bx = blockIdx.x * 128, by = blockIdx.y * 128;
    const int tid = threadIdx.x;
    const int arow = tid >> 1, ak = (tid & 1) * 4;
    const int brow = tid >> 5, bcol = (tid & 31) * 4;
    const int tx = tid & 15, ty = tid >> 4;
    float acc[8][8] = {};

    const float* aptr = &A[(size_t)(by + arow) * K + ak];
    const float* bptr = &B[(size_t)brow * Nc + bx + bcol];

    float4 a4 = *reinterpret_cast<const float4*>(aptr);
    float4 b4 = *reinterpret_cast<const float4*>(bptr);
    As[0][ak + 0][arow] = a4.x; As[0][ak + 1][arow] = a4.y;
    As[0][ak + 2][arow] = a4.z; As[0][ak + 3][arow] = a4.w;
    *reinterpret_cast<float4*>(&Bs[0][brow][bcol]) = b4;
    __syncthreads();

    const int nIter = K / 8;
    for (int it = 0; it < nIter; it++) {
        int cur = it & 1, nxt = cur ^ 1;
        if (it + 1 < nIter) {
            a4 = *reinterpret_cast<const float4*>(aptr + (size_t)(it + 1) * 8);
            b4 = *reinterpret_cast<const float4*>(bptr + (size_t)(it + 1) * 8 * Nc);
        }
        #pragma unroll
        for (int k = 0; k < 8; k++) {
            float4 a0 = *reinterpret_cast<const float4*>(&As[cur][k][ty * 8]);
            float4 a1 = *reinterpret_cast<const float4*>(&As[cur][k][ty * 8 + 4]);
            float4 r0 = *reinterpret_cast<const float4*>(&Bs[cur][k][tx * 8]);
            float4 r1 = *reinterpret_cast<const float4*>(&Bs[cur][k][tx * 8 + 4]);
            float av[8] = {a0.x, a0.y, a0.z, a0.w, a1.x, a1.y, a1.z, a1.w};
            float bv[8] = {r0.x, r0.y, r0.z, r0.w, r1.x, r1.y, r1.z, r1.w};
            #pragma unroll
            for (int i = 0; i < 8; i++)
                #pragma unroll
                for (int j = 0; j < 8; j++) acc[i][j] += av[i] * bv[j];
        }
        if (it + 1 < nIter) {
            As[nxt][ak + 0][arow] = a4.x; As[nxt][ak + 1][arow] = a4.y;
            As[nxt][ak + 2][arow] = a4.z; As[nxt][ak + 3][arow] = a4.w;
            *reinterpret_cast<float4*>(&Bs[nxt][brow][bcol]) = b4;
        }
        __syncthreads();
    }

    if (bias) {
        float4 bb0 = *reinterpret_cast<const float4*>(&bias[bx + tx * 8]);
        float4 bb1 = *reinterpret_cast<const float4*>(&bias[bx + tx * 8 + 4]);
        #pragma unroll
        for (int i = 0; i < 8; i++) {
            acc[i][0] += bb0.x; acc[i][1] += bb0.y; acc[i][2] += bb0.z; acc[i][3] += bb0.w;
            acc[i][4] += bb1.x; acc[i][5] += bb1.y; acc[i][6] += bb1.z; acc[i][7] += bb1.w;
        }
    }
    #pragma unroll
    for (int i = 0; i < 8; i++) {
        float* crow = &C[(size_t)(by + ty * 8 + i) * ldc + bx + tx * 8];
        *reinterpret_cast<float4*>(crow)     = make_float4(acc[i][0], acc[i][1], acc[i][2], acc[i][3]);
        *reinterpret_cast<float4*>(crow + 4) = make_float4(acc[i][4], acc[i][5], acc[i][6], acc[i][7]);
    }
    if (SCORES) {
        const int head = blockIdx.x;
        const int nhs = Nc >> 7;
        float w1[8], w2[8];
        #pragma unroll
        for (int j = 0; j < 8; j++) {
            w1[j] = asrc[head * H + tx * 8 + j];
            w2[j] = adst[head * H + tx * 8 + j];
        }
        #pragma unroll
        for (int i = 0; i < 8; i++) {
            float s1 = 0.f, s2 = 0.f;
            #pragma unroll
            for (int j = 0; j < 8; j++) { s1 += acc[i][j] * w1[j]; s2 += acc[i][j] * w2[j]; }
            #pragma unroll
            for (int o = 8; o; o >>= 1) {
                s1 += __shfl_xor_sync(0xffffffffu, s1, o);
                s2 += __shfl_xor_sync(0xffffffffu, s2, o);
            }
            if (tx == 0) {
                int r = by + ty * 8 + i;
                als[r * nhs + head] = s1;
                ald[r * nhs + head] = s2;
            }
        }
    }
}

// ---------------- bf16-split tensor-core GEMM (layer-2) ----------------------
// xp2[M,128] = x2[M,512] @ W2[512,128]; fused score dots als2/ald2.
// Split precision: A = Ah + Al, B = Bh + Bl (bf16 hi + bf16 residual);
// D = Ah*Bh + Al*Bh + Ah*Bl via mma.sync m16n8k16 — dropped Al*Bl ~2^-16 rel.
// Block: 128x128 tile, 8 warps (4 warpM x 2 warpN), warp tile 32x64.
// Fragment regs are single aligned 32-bit LDS from bf16x2-pair smem layouts.
#define G2_K 512
#define G2_N 128

__device__ __forceinline__ void mma16816(float* c, const uint32_t* a, const uint32_t* b) {
    asm volatile(
        "mma.sync.aligned.m16n8k16.row.col.f32.bf16.bf16.f32 "
        "{%0,%1,%2,%3}, {%4,%5,%6,%7}, {%8,%9}, {%0,%1,%2,%3};\n"
        : "+f"(c[0]), "+f"(c[1]), "+f"(c[2]), "+f"(c[3])
        : "r"(a[0]), "r"(a[1]), "r"(a[2]), "r"(a[3]), "r"(b[0]), "r"(b[1]));
}

__global__ __launch_bounds__(256) void mma_gemm2(
    const float* __restrict__ A,    // [M,512]
    const float* __restrict__ B,    // [512,128]
    float* __restrict__ C,          // [M,128]
    const float* __restrict__ asrc, const float* __restrict__ adst,
    float* __restrict__ als, float* __restrict__ ald) {
    __shared__ __nv_bfloat162 Ah[128][8], Al[128][8];   // [row][k-pair]
    __shared__ __nv_bfloat162 Bh[128][8], Bl[128][8];   // [n][k-pair] (B transposed)
    __shared__ float s_s1[128][2], s_s2[128][2];

    const int tid = threadIdx.x;
    const int wid = tid >> 5, lane = tid & 31;
    const int g = lane >> 2, th = lane & 3;
    const int warpM = wid & 3, warpN = wid >> 2;        // 4 x 2 warp grid
    const int rowBase = blockIdx.x * 128;

    float acc[2][8][4];
    #pragma unroll
    for (int i = 0; i < 2; i++)
        #pragma unroll
        for (int j = 0; j < 8; j++)
            #pragma unroll
            for (int q = 0; q < 4; q++) acc[i][j][q] = 0.f;

    // loader roles
    const int la_r = tid >> 1, la_k = (tid & 1) * 8;     // A: row, k-offset (8 floats)
    const int lb_n = tid & 127, lb_k = (tid >> 7) * 8;   // B: col n, k-offset (8 floats)

    for (int k0 = 0; k0 < G2_K; k0 += 16) {
        // A tile 128x16 -> hi/lo pairs
        {
            const float* src = A + (size_t)(rowBase + la_r) * G2_K + k0 + la_k;
            float4 f0 = *reinterpret_cast<const float4*>(src);
            float4 f1 = *reinterpret_cast<const float4*>(src + 4);
            float vv[8] = {f0.x, f0.y, f0.z, f0.w, f1.x, f1.y, f1.z, f1.w};
            #pragma unroll
            for (int i = 0; i < 4; i++) {
                __nv_bfloat16 h0 = __float2bfloat16(vv[2 * i]);
                __nv_bfloat16 h1 = __float2bfloat16(vv[2 * i + 1]);
                __nv_bfloat16 l0 = __float2bfloat16(vv[2 * i] - __bfloat162float(h0));
                __nv_bfloat16 l1 = __float2bfloat16(vv[2 * i + 1] - __bfloat162float(h1));
                Ah[la_r][la_k / 2 + i] = __nv_bfloat162(h0, h1);
                Al[la_r][la_k / 2 + i] = __nv_bfloat162(l0, l1);
            }
        }
        // B tile 16x128 -> transposed hi/lo pairs (per-k coalesced gmem reads)
        {
            float vv[8];
            #pragma unroll
            for (int i = 0; i < 8; i++)
                vv[i] = B[(size_t)(k0 + lb_k + i) * G2_N + lb_n];
            #pragma unroll
            for (int i = 0; i < 4; i++) {
                __nv_bfloat16 h0 = __float2bfloat16(vv[2 * i]);
                __nv_bfloat16 h1 = __float2bfloat16(vv[2 * i + 1]);
                __nv_bfloat16 l0 = __float2bfloat16(vv[2 * i] - __bfloat162float(h0));
                __nv_bfloat16 l1 = __float2bfloat16(vv[2 * i + 1] - __bfloat162float(h1));
                Bh[lb_n][lb_k / 2 + i] = __nv_bfloat162(h0, h1);
                Bl[lb_n][lb_k / 2 + i] = __nv_bfloat162(l0, l1);
            }
        }
        __syncthreads();
        #pragma unroll
        for (int i = 0; i < 2; i++) {
            const int ar = warpM * 32 + i * 16;
            uint32_t ah[4], al_[4];
            ah[0]  = *reinterpret_cast<const uint32_t*>(&Ah[ar + g][th]);
            ah[1]  = *reinterpret_cast<const uint32_t*>(&Ah[ar + g + 8][th]);
            ah[2]  = *reinterpret_cast<const uint32_t*>(&Ah[ar + g][th + 4]);
            ah[3]  = *reinterpret_cast<const uint32_t*>(&Ah[ar + g + 8][th + 4]);
            al_[0] = *reinterpret_cast<const uint32_t*>(&Al[ar + g][th]);
            al_[1] = *reinterpret_cast<const uint32_t*>(&Al[ar + g + 8][th]);
            al_[2] = *reinterpret_cast<const uint32_t*>(&Al[ar + g][th + 4]);
            al_[3] = *reinterpret_cast<const uint32_t*>(&Al[ar + g + 8][th + 4]);
            #pragma unroll
            for (int j = 0; j < 8; j++) {
                const int bc = warpN * 64 + j * 8;
                uint32_t bh[2], bl[2];
                bh[0] = *reinterpret_cast<const uint32_t*>(&Bh[bc + g][th]);
                bh[1] = *reinterpret_cast<const uint32_t*>(&Bh[bc + g][th + 4]);
                bl[0] = *reinterpret_cast<const uint32_t*>(&Bl[bc + g][th]);
                bl[1] = *reinterpret_cast<const uint32_t*>(&Bl[bc + g][th + 4]);
                mma16816(acc[i][j], ah, bh);
                mma16816(acc[i][j], al_, bh);
                mma16816(acc[i][j], ah, bl);
            }
        }
        __syncthreads();
    }

    // epilogue: write C and fused score dots
    #pragma unroll
    for (int i = 0; i < 2; i++) {
        const int lr0 = warpM * 32 + i * 16 + g;
        const int lr1 = lr0 + 8;
        float s1a = 0.f, s1b = 0.f, s2a = 0.f, s2b = 0.f;
        #pragma unroll
        for (int j = 0; j < 8; j++) {
            const int cc = warpN * 64 + j * 8 + th * 2;
            float w10 = asrc[cc], w11 = asrc[cc + 1];
            float w20 = adst[cc], w21 = adst[cc + 1];
            float e0 = acc[i][j][0], e1 = acc[i][j][1];
            float e2 = acc[i][j][2], e3 = acc[i][j][3];
            s1a += e0 * w10 + e1 * w11;  s2a += e0 * w20 + e1 * w21;
            s1b += e2 * w10 + e3 * w11;  s2b += e2 * w20 + e3 * w21;
            *reinterpret_cast<float2*>(&C[(size_t)(rowBase + lr0) * G2_N + cc]) = make_float2(e0, e1);
            *reinterpret_cast<float2*>(&C[(size_t)(rowBase + lr1) * G2_N + cc]) = make_float2(e2, e3);
        }
        #pragma unroll
        for (int o = 1; o <= 2; o <<= 1) {
            s1a += __shfl_xor_sync(0xffffffffu, s1a, o);
            s1b += __shfl_xor_sync(0xffffffffu, s1b, o);
            s2a += __shfl_xor_sync(0xffffffffu, s2a, o);
            s2b += __shfl_xor_sync(0xffffffffu, s2b, o);
        }
        if (th == 0) {
            s_s1[lr0][warpN] = s1a;  s_s1[lr1][warpN] = s1b;
            s_s2[lr0][warpN] = s2a;  s_s2[lr1][warpN] = s2b;
        }
    }
    __syncthreads();
    if (tid < 128) {
        als[rowBase + tid] = s_s1[tid][0] + s_s1[tid][1];
        ald[rowBase + tid] = s_s2[tid][0] + s_s2[tid][1];
    }
}

// ---------------- CSR build (by dst) ----------------------------------------
__global__ void hist_kernel(const int* __restrict__ ei) {
    int e = blockIdx.x * blockDim.x + threadIdx.x;
    if (e < E_EDGES) atomicAdd(&g_deg[ei[E_EDGES + e]], 1);
}
__global__ void scan_kernel() {
    __shared__ int part[1024];
    int tid = threadIdx.x;
    int base = tid * 32;
    int local[32];
    int s = 0;
    #pragma unroll
    for (int i = 0; i < 32; i++) { local[i] = s; s += g_deg[base + i]; }
    part[tid] = s;
    __syncthreads();
    for (int off = 1; off < 1024; off <<= 1) {
        int v = 0;
        if (tid >= off) v = part[tid - off];
        __syncthreads();
        part[tid] += v;
        __syncthreads();
    }
    int pre = (tid == 0) ? 0 : part[tid - 1];
    #pragma unroll
    for (int i = 0; i < 32; i++) g_off[base + i] = pre + local[i];
    if (tid == 1023) g_off[N_NODES] = part[1023];
}
__global__ void scatter_kernel(const int* __restrict__ ei) {
    int e = blockIdx.x * blockDim.x + threadIdx.x;
    if (e < E_EDGES) {
        int s = ei[e];
        int d = ei[E_EDGES + e];
        int pos = g_off[d] + atomicAdd(&g_cur[d], 1);
        g_csr[pos] = s;
        g_csr_rid[pos] = g_rowid[s];
    }
}

// ---------------- GAT aggregation: one warp per destination node -------------
template <int NH, bool IND>
__global__ __launch_bounds__(256) void gat_agg(const float* __restrict__ xp,
                                               const float* __restrict__ als,
                                               const float* __restrict__ ald,
                                               const float* __restrict__ bias,
                                               float* __restrict__ out,
                                               const int* __restrict__ csr_idx) {
    __shared__ float s_als[IND ? TAB_ROWS * NH : 1];
    if (IND) {
        for (int i = threadIdx.x; i < TAB_ROWS * NH; i += 256) s_als[i] = als[i];
        __syncthreads();
    }
    int d = (blockIdx.x * blockDim.x + threadIdx.x) >> 5;
    int lane = threadIdx.x & 31;
    if (d >= N_NODES) return;
    const int beg = g_off[d], end = g_off[d + 1];
    const int rd = IND ? g_rowid[d] : d;
    float aldv[NH], denom[NH];
    float4 acc[NH];
    #pragma unroll
    for (int h = 0; h < NH; h++) {
        aldv[h] = ald[rd * NH + h];
        denom[h] = 0.f;
        acc[h] = make_float4(0.f, 0.f, 0.f, 0.f);
    }
    const float4* xp4 = reinterpret_cast<const float4*>(xp);

    int rs_cur = rd;
    float sc_cur[NH];
    float4 v_cur[NH];
    #pragma unroll
    for (int h = 0; h < NH; h++) {
        sc_cur[h] = IND ? s_als[rs_cur * NH + h] : als[rs_cur * NH + h];
        v_cur[h] = xp4[(size_t)rs_cur * (NH * 32) + h * 32 + lane];
    }
    #pragma unroll 1
    for (int i = beg; i <= end; i++) {
        int rs_nxt = 0;
        float sc_nxt[NH];
        float4 v_nxt[NH];
        if (i < end) {
            rs_nxt = csr_idx[i];
            #pragma unroll
            for (int h = 0; h < NH; h++) {
                sc_nxt[h] = IND ? s_als[rs_nxt * NH + h] : als[rs_nxt * NH + h];
                v_nxt[h] = xp4[(size_t)rs_nxt * (NH * 32) + h * 32 + lane];
            }
        }
        #pragma unroll
        for (int h = 0; h < NH; h++) {
            float e = __expf(lrelu02(sc_cur[h] + aldv[h]));
            denom[h] += e;
            acc[h].x += v_cur[h].x * e;
            acc[h].y += v_cur[h].y * e;
            acc[h].z += v_cur[h].z * e;
            acc[h].w += v_cur[h].w * e;
        }
        rs_cur = rs_nxt;
        #pragma unroll
        for (int h = 0; h < NH; h++) { sc_cur[h] = sc_nxt[h]; v_cur[h] = v_nxt[h]; }
    }
    #pragma unroll
    for (int h = 0; h < NH; h++) {
        int c = h * H + lane * 4;
        float inv = 1.f / denom[h];
        float4 bv = *reinterpret_cast<const float4*>(&bias[c]);
        float4 o;
        o.x = eluf(acc[h].x * inv + bv.x);
        o.y = eluf(acc[h].y * inv + bv.y);
        o.z = eluf(acc[h].z * inv + bv.z);
        o.w = eluf(acc[h].w * inv + bv.w);
        *reinterpret_cast<float4*>(&out[(size_t)d * (NH * H) + c]) = o;
    }
}

// ---------------- fused masked mean pool + output head -----------------------
__global__ __launch_bounds__(128) void pool_head_kernel(
    const int* __restrict__ m_idx, const float* __restrict__ x,
    const float* __restrict__ Wo1, const float* __restrict__ bo1,
    const float* __restrict__ Wo2, const float* __restrict__ bo2,
    float* __restrict__ out) {
    int g = blockIdx.x, c = threadIdx.x;
    __shared__ int msk[MAXN];
    __shared__ float p[H];
    __shared__ float red[H];
    if (c < MAXN) msk[c] = (m_idx[g * MAXN + c] >= 1) ? 1 : 0;
    __syncthreads();
    float s = 0.f;
    int cnt = 0;
    #pragma unroll 4
    for (int n = 0; n < MAXN; n++) {
        if (msk[n]) { s += x[(size_t)(g * MAXN + n) * H + c]; cnt++; }
    }
    p[c] = s / (float)cnt;
    __syncthreads();
    float h = bo1[c];
    #pragma unroll 4
    for (int k = 0; k < H; k++) h += p[k] * Wo1[k * H + c];
    h = h > 0.f ? h : 0.01f * h;
    red[c] = h * Wo2[c];
    __syncthreads();
    for (int o = 64; o; o >>= 1) { if (c < o) red[c] += red[c + o]; __syncthreads(); }
    if (c == 0) out[g] = red[0] + bo2[0];
}

// ---------------- launch ------------------------------------------------------
extern "C" void kernel_launch(void* const* d_in, const int* in_sizes, int n_in,
                              void* d_out, int out_size) {
    const void* p[27];
    if (n_in >= 4 && in_sizes[2] == N_NODES) {
        static const int mp[27] = {0, 1, 4, 5, 6, 7, 8, 9, 10, 11, 12, 13, 14,
                                   15, 16, 17, 18, 19, 20, 21, 22, 23, 24, 25, 26, 2, 3};
        for (int i = 0; i < 27; i++) p[i] = d_in[mp[i]];
    } else {
        for (int i = 0; i < 27; i++) p[i] = d_in[i];
    }
    const float* t       = (const float*)p[0];
    const float* v       = (const float*)p[1];
    const float* Wt      = (const float*)p[2];
    const float* bt      = (const float*)p[3];
    const float* Wv      = (const float*)p[4];
    const float* bv      = (const float*)p[5];
    const float* emb     = (const float*)p[6];
    const float* Wnode   = (const float*)p[7];
    const float* bnode   = (const float*)p[8];
    const float* Wstart  = (const float*)p[9];
    const float* bstart  = (const float*)p[10];
    const float* ln_g    = (const float*)p[11];
    const float* ln_b    = (const float*)p[12];
    const float* W1      = (const float*)p[13];
    const float* a_src1  = (const float*)p[14];
    const float* a_dst1  = (const float*)p[15];
    const float* b1      = (const float*)p[16];
    const float* W2      = (const float*)p[17];
    const float* a_src2  = (const float*)p[18];
    const float* a_dst2  = (const float*)p[19];
    const float* b2      = (const float*)p[20];
    const float* Wo1     = (const float*)p[21];
    const float* bo1     = (const float*)p[22];
    const float* Wo2     = (const float*)p[23];
    const float* bo2     = (const float*)p[24];
    const int*   m_idx   = (const int*)p[25];
    const int*   ei      = (const int*)p[26];

    float* xtab;   cudaGetSymbolAddress((void**)&xtab,   g_xtab);
    float* xp1;    cudaGetSymbolAddress((void**)&xp1,    g_xp1);
    float* als1;   cudaGetSymbolAddress((void**)&als1,   g_als1);
    float* ald1;   cudaGetSymbolAddress((void**)&ald1,   g_ald1);
    float* x2buf;  cudaGetSymbolAddress((void**)&x2buf,  g_x2);
    float* xp2;    cudaGetSymbolAddress((void**)&xp2,    g_xp2);
    float* als2;   cudaGetSymbolAddress((void**)&als2,   g_als2);
    float* ald2;   cudaGetSymbolAddress((void**)&ald2,   g_ald2);
    float* x3buf;  cudaGetSymbolAddress((void**)&x3buf,  g_x3);
    int*   csr;    cudaGetSymbolAddress((void**)&csr,    g_csr);
    int*   csrrid; cudaGetSymbolAddress((void**)&csrrid, g_csr_rid);

    // 0-3: rowid (+deg/cur reset) then CSR build
    rowid_kernel<<<(N_NODES + 255) / 256, 256>>>(m_idx);
    hist_kernel<<<E_EDGES / 256, 256>>>(ei);
    scan_kernel<<<1, 1024>>>();
    scatter_kernel<<<E_EDGES / 256, 256>>>(ei);

    // 4: fused encoder (start rows x4/block + embW rows), LN in-block
    encoder_kernel<<<128 + NTYPE + 1, 128>>>(t, v, Wt, bt, Wv, bv, Wstart, bstart,
                                             emb, Wnode, bnode, ln_g, ln_b);

    // 5: GAT layer 1 projection over the 640-row table, scores fused per-head
    sgemm128<true><<<dim3(HEADS1 * H / 128, TAB_ROWS / 128), 256>>>(
        xtab, W1, xp1, TAB_ROWS, HEADS1 * H, H, HEADS1 * H, nullptr,
        a_src1, a_dst1, als1, ald1);
    // 6: layer-1 aggregation
    gat_agg<HEADS1, true><<<(N_NODES * 32) / 256, 256>>>(xp1, als1, ald1, b1, x2buf, csrrid);

    // 7: GAT layer 2 — bf16-split tensor-core GEMM with fused score epilogue
    mma_gemm2<<<N_NODES / 128, 256>>>(x2buf, W2, xp2, a_src2, a_dst2, als2, ald2);
    // 8: layer-2 aggregation
    gat_agg<1, false><<<(N_NODES * 32) / 256, 256>>>(xp2, als2, ald2, b2, x3buf, csr);

    // 9: fused pool + head
    pool_head_kernel<<<G_NUM, H>>>(m_idx, x3buf, Wo1, bo1, Wo2, bo2, (float*)d_out);
}